// round 1
// baseline (speedup 1.0000x reference)
#include <cuda_runtime.h>
#include <math.h>

// Problem constants
#define B   512     // batch
#define IU  8       // in_unit
#define C   1152    // in_channel
#define J   10      // num_unit
#define S   16      // unit_size
#define NR  3       // routing iterations

// Tiling
#define CC  8            // c's per block
#define NC  (C/CC)       // 144 c-chunks
#define BT  16           // b's per block
#define NB  (B/BT)       // 32 b-tiles
#define R   (B*IU)       // 4096 rows for transpose view

// Scratch (allocation-free: __device__ globals)
__device__ __align__(16) float g_xT[(size_t)C*B*IU];   // [c][b][i]  18.9 MB
__device__ float g_b[C*J];                              // routing logits
__device__ float g_cc[C*J];                             // softmax coefficients
__device__ float g_sp[NC][J*B*S];                       // partial s   47 MB
__device__ float g_v[J*B*S];                            // v [j][b][s]
__device__ float g_bp[NB][C*J];                         // partial delta_b

// ---------------------------------------------------------------------------
// Transpose x[b][i][c] -> g_xT[c][b*8+i]  (2D transpose of [R=4096][C=1152])
// ---------------------------------------------------------------------------
__global__ void k_transpose(const float* __restrict__ x) {
    __shared__ float t[32][33];
    int cb = blockIdx.x * 32, rb = blockIdx.y * 32;
    int tx = threadIdx.x, ty = threadIdx.y;
    #pragma unroll
    for (int k = 0; k < 32; k += 8)
        t[ty + k][tx] = x[(size_t)(rb + ty + k) * C + cb + tx];
    __syncthreads();
    #pragma unroll
    for (int k = 0; k < 32; k += 8)
        g_xT[(size_t)(cb + ty + k) * R + rb + tx] = t[tx][ty + k];
}

__global__ void k_zero_b() {
    int i = blockIdx.x * blockDim.x + threadIdx.x;
    if (i < C * J) g_b[i] = 0.f;
}

// ---------------------------------------------------------------------------
// b += sum(partials)/B (if do_update), then cc = softmax_j(b) per c-row.
// Deterministic reduction order (no fp atomics to global).
// ---------------------------------------------------------------------------
__global__ void k_update_softmax(int do_update) {
    int c = blockIdx.x * blockDim.x + threadIdx.x;
    if (c >= C) return;
    float bv[J];
    #pragma unroll
    for (int j = 0; j < J; j++) {
        float v = g_b[c * J + j];
        if (do_update) {
            float d = 0.f;
            #pragma unroll 4
            for (int p = 0; p < NB; p++) d += g_bp[p][c * J + j];
            v += d * (1.f / B);
            g_b[c * J + j] = v;
        }
        bv[j] = v;
    }
    float m = bv[0];
    #pragma unroll
    for (int j = 1; j < J; j++) m = fmaxf(m, bv[j]);
    float sum = 0.f;
    #pragma unroll
    for (int j = 0; j < J; j++) { bv[j] = expf(bv[j] - m); sum += bv[j]; }
    float inv = 1.f / sum;
    #pragma unroll
    for (int j = 0; j < J; j++) g_cc[c * J + j] = bv[j] * inv;
}

// ---------------------------------------------------------------------------
// Shared tile loaders (W chunk 40KB + x tile 4KB, both SMEM-staged so the
// inner loop issues zero LDG — LDG issue floor 1.82cyc/SM would dominate).
// Wsm layout float4[cl][j][half][s]: warp (16 s-lanes) reads consecutive
// float4s -> 2-phase smem access, no 4-way bank conflicts.
// ---------------------------------------------------------------------------
__device__ __forceinline__ void load_tiles(
    const float* __restrict__ W, int c0, int b0, int tid,
    float4 (*Wsm)[J][2][S], float4 (*xsm)[BT][2])
{
    const float4* Wg = (const float4*)(W + (size_t)c0 * J * S * IU);
    #pragma unroll
    for (int g = tid; g < CC * J * S * 2; g += 256) {
        float4 w = Wg[g];
        int h  = g & 1;
        int s  = (g >> 1) & 15;
        int j  = (g >> 5) % J;
        int cl = g / (J * S * 2);
        Wsm[cl][j][h][s] = w;
    }
    #pragma unroll
    for (int g = tid; g < CC * BT * 2; g += 256) {
        int cl  = g >> 5;
        int rem = g & 31;   // bl*2 + h
        xsm[cl][rem >> 1][rem & 1] =
            ((const float4*)(g_xT + (size_t)(c0 + cl) * R + (size_t)b0 * IU))[rem];
    }
}

// ---------------------------------------------------------------------------
// K_s: partial s[j,b,s] = sum_{c in chunk} cc[c,j] * u_hat[c,j,b,s]
// thread = (bl = tid>>4, s_ = tid&15); per-thread 10 j-accumulators.
// ---------------------------------------------------------------------------
__global__ void __launch_bounds__(256) k_s(const float* __restrict__ W) {
    __shared__ float4 Wsm[CC][J][2][S];
    __shared__ float4 xsm[CC][BT][2];
    __shared__ float  ccs[CC][J];
    int c0 = blockIdx.x * CC;
    int b0 = blockIdx.y * BT;
    int tid = threadIdx.x;

    load_tiles(W, c0, b0, tid, Wsm, xsm);
    if (tid < CC * J) ccs[tid / J][tid % J] = g_cc[(c0 + tid / J) * J + tid % J];
    __syncthreads();

    int s_ = tid & 15;
    int bl = tid >> 4;
    float acc[J];
    #pragma unroll
    for (int j = 0; j < J; j++) acc[j] = 0.f;

    #pragma unroll
    for (int cl = 0; cl < CC; ++cl) {
        float4 xa = xsm[cl][bl][0];
        float4 xb = xsm[cl][bl][1];
        #pragma unroll
        for (int j = 0; j < J; j++) {
            float4 wa = Wsm[cl][j][0][s_];
            float4 wb = Wsm[cl][j][1][s_];
            float u = wa.x*xa.x + wa.y*xa.y + wa.z*xa.z + wa.w*xa.w
                    + wb.x*xb.x + wb.y*xb.y + wb.z*xb.z + wb.w*xb.w;
            acc[j] = fmaf(ccs[cl][j], u, acc[j]);
        }
    }
    float* sp = g_sp[blockIdx.x];
    #pragma unroll
    for (int j = 0; j < J; j++)
        sp[(j * B + b0 + bl) * S + s_] = acc[j];
}

// ---------------------------------------------------------------------------
// K_b: partial delta_b[c,j] = sum_{b in tile, s} v[j,b,s] * u_hat[c,j,b,s]
// shfl-reduce over the 16 s-lanes, then 2 lanes/warp smem-atomic into dsm.
// ---------------------------------------------------------------------------
__global__ void __launch_bounds__(256) k_b(const float* __restrict__ W) {
    __shared__ float4 Wsm[CC][J][2][S];
    __shared__ float4 xsm[CC][BT][2];
    __shared__ float  dsm[J];
    int c0 = blockIdx.x * CC;
    int b0 = blockIdx.y * BT;
    int tid = threadIdx.x;

    load_tiles(W, c0, b0, tid, Wsm, xsm);
    if (tid < J) dsm[tid] = 0.f;
    __syncthreads();

    int s_ = tid & 15;
    int bl = tid >> 4;
    int b  = b0 + bl;
    float vv[J];
    #pragma unroll
    for (int j = 0; j < J; j++) vv[j] = g_v[(j * B + b) * S + s_];

    for (int cl = 0; cl < CC; ++cl) {
        float4 xa = xsm[cl][bl][0];
        float4 xb = xsm[cl][bl][1];
        #pragma unroll
        for (int j = 0; j < J; j++) {
            float4 wa = Wsm[cl][j][0][s_];
            float4 wb = Wsm[cl][j][1][s_];
            float u = wa.x*xa.x + wa.y*xa.y + wa.z*xa.z + wa.w*xa.w
                    + wb.x*xb.x + wb.y*xb.y + wb.z*xb.z + wb.w*xb.w;
            float p = vv[j] * u;
            p += __shfl_xor_sync(0xffffffffu, p, 1);
            p += __shfl_xor_sync(0xffffffffu, p, 2);
            p += __shfl_xor_sync(0xffffffffu, p, 4);
            p += __shfl_xor_sync(0xffffffffu, p, 8);
            if (s_ == 0) atomicAdd(&dsm[j], p);
        }
        __syncthreads();
        if (tid < J) {
            g_bp[blockIdx.y][(c0 + cl) * J + tid] = dsm[tid];
            dsm[tid] = 0.f;
        }
        __syncthreads();
    }
}

// ---------------------------------------------------------------------------
// Reduce 144 partials -> s, squash over unit_size (16 lanes, shfl), -> v.
// Final iteration also writes output [B][J][S].
// ---------------------------------------------------------------------------
__global__ void k_rs(float* __restrict__ out) {
    int idx = blockIdx.x * blockDim.x + threadIdx.x;   // exactly J*B*S threads
    float sum = 0.f;
    #pragma unroll 8
    for (int p = 0; p < NC; p++) sum += g_sp[p][idx];
    float msq = sum * sum;
    msq += __shfl_xor_sync(0xffffffffu, msq, 1);
    msq += __shfl_xor_sync(0xffffffffu, msq, 2);
    msq += __shfl_xor_sync(0xffffffffu, msq, 4);
    msq += __shfl_xor_sync(0xffffffffu, msq, 8);
    // squash: s * msq/((1+msq)*sqrt(msq)) == s * sqrt(msq)/(1+msq)
    float v = sum * sqrtf(msq) / (1.f + msq);
    g_v[idx] = v;
    if (out) {
        int s_ = idx & 15;
        int jb = idx >> 4;
        int b  = jb & (B - 1);
        int j  = jb >> 9;
        out[(b * J + j) * S + s_] = v;
    }
}

// ---------------------------------------------------------------------------
extern "C" void kernel_launch(void* const* d_in, const int* in_sizes, int n_in,
                              void* d_out, int out_size) {
    const float* x = (const float*)d_in[0];   // [512][8][1152]
    const float* W = (const float*)d_in[1];   // [1152][10][16][8]
    float* out = (float*)d_out;               // [512][10][16]

    k_transpose<<<dim3(C / 32, R / 32), dim3(32, 8)>>>(x);
    k_zero_b<<<(C * J + 255) / 256, 256>>>();

    for (int t = 0; t < NR; t++) {
        if (t > 0) k_b<<<dim3(NC, NB), 256>>>(W);
        k_update_softmax<<<(C + 127) / 128, 128>>>(t > 0 ? 1 : 0);
        k_s<<<dim3(NC, NB), 256>>>(W);
        k_rs<<<(J * B * S) / 256, 256>>>(t == NR - 1 ? out : nullptr);
    }
}

// round 2
// speedup vs baseline: 2.7997x; 2.7997x over previous
#include <cuda_runtime.h>
#include <math.h>

// Problem constants
#define B   512     // batch
#define IU  8       // in_unit
#define C   1152    // in_channel
#define J   10      // num_unit
#define S   16      // unit_size
#define NR  3       // routing iterations

// Tiling
#define CC  8            // c's per block
#define NC  (C/CC)       // 144 c-chunks
#define BT  64           // b's per block (4 per thread, 16 s-lanes)
#define NB  (B/BT)       // 8 b-tiles
#define BPT 4            // b's per thread
#define R   (B*IU)       // 4096 rows for transpose view

// Scratch (allocation-free: __device__ globals)
__device__ __align__(16) float g_xT[(size_t)C*B*IU];   // [c][b][i]  18.9 MB
__device__ float g_b[C*J];                              // routing logits
__device__ float g_cc[C*J];                             // softmax coefficients
__device__ float g_sp[NC][J*B*S];                       // partial s   47 MB
__device__ float g_v[J*B*S];                            // v [j][b][s]
__device__ float g_bp[NB][C*J];                         // partial delta_b

struct SMemS {
    float4 Wsm[CC][J][2][S];   // 40 KB (pre-scaled by cc in k_s)
    float4 xsm[CC][BT][2];     // 16 KB
};
struct SMemB {
    float4 Wsm[CC][J][2][S];
    float4 xsm[CC][BT][2];
    float  dsm[CC][J];
};

// ---------------------------------------------------------------------------
// Transpose x[b][i][c] -> g_xT[c][b*8+i]  (2D transpose of [R=4096][C=1152])
// ---------------------------------------------------------------------------
__global__ void k_transpose(const float* __restrict__ x) {
    __shared__ float t[32][33];
    int cb = blockIdx.x * 32, rb = blockIdx.y * 32;
    int tx = threadIdx.x, ty = threadIdx.y;
    #pragma unroll
    for (int k = 0; k < 32; k += 8)
        t[ty + k][tx] = x[(size_t)(rb + ty + k) * C + cb + tx];
    __syncthreads();
    #pragma unroll
    for (int k = 0; k < 32; k += 8)
        g_xT[(size_t)(cb + ty + k) * R + rb + tx] = t[tx][ty + k];
}

__global__ void k_zero_b() {
    int i = blockIdx.x * blockDim.x + threadIdx.x;
    if (i < C * J) g_b[i] = 0.f;
}

// ---------------------------------------------------------------------------
// b += sum(partials)/B (if do_update), then cc = softmax_j(b) per c-row.
// ---------------------------------------------------------------------------
__global__ void k_update_softmax(int do_update) {
    int c = blockIdx.x * blockDim.x + threadIdx.x;
    if (c >= C) return;
    float bv[J];
    #pragma unroll
    for (int j = 0; j < J; j++) {
        float v = g_b[c * J + j];
        if (do_update) {
            float d = 0.f;
            #pragma unroll
            for (int p = 0; p < NB; p++) d += g_bp[p][c * J + j];
            v += d * (1.f / B);
            g_b[c * J + j] = v;
        }
        bv[j] = v;
    }
    float m = bv[0];
    #pragma unroll
    for (int j = 1; j < J; j++) m = fmaxf(m, bv[j]);
    float sum = 0.f;
    #pragma unroll
    for (int j = 0; j < J; j++) { bv[j] = expf(bv[j] - m); sum += bv[j]; }
    float inv = 1.f / sum;
    #pragma unroll
    for (int j = 0; j < J; j++) g_cc[c * J + j] = bv[j] * inv;
}

// ---------------------------------------------------------------------------
// Tile loaders. Wsm float4[cl][j][half][s]: warp (16 s-lanes) reads
// consecutive float4s -> conflict-free. scale_by_cc pre-multiplies W rows
// by routing coefficients (k_s only).
// ---------------------------------------------------------------------------
template <int SCALE>
__device__ __forceinline__ void load_tiles(
    const float* __restrict__ W, int c0, int b0, int tid,
    float4 (*Wsm)[J][2][S], float4 (*xsm)[BT][2])
{
    const float4* Wg = (const float4*)(W + (size_t)c0 * J * S * IU);
    #pragma unroll
    for (int g = tid; g < CC * J * S * 2; g += 256) {
        float4 w = Wg[g];
        int h  = g & 1;
        int s  = (g >> 1) & 15;
        int j  = (g >> 5) % J;
        int cl = g / (J * S * 2);
        if (SCALE) {
            float cv = __ldg(&g_cc[(c0 + cl) * J + j]);
            w.x *= cv; w.y *= cv; w.z *= cv; w.w *= cv;
        }
        Wsm[cl][j][h][s] = w;
    }
    #pragma unroll
    for (int g = tid; g < CC * BT * 2; g += 256) {
        int cl  = g >> 7;         // 64 b * 2 halves = 128 float4 per c
        int rem = g & 127;        // bl*2 + h
        xsm[cl][rem >> 1][rem & 1] =
            ((const float4*)(g_xT + (size_t)(c0 + cl) * R + (size_t)b0 * IU))[rem];
    }
}

// ---------------------------------------------------------------------------
// K_s: partial s[j,b,s] = sum_{c in chunk} cc[c,j] * u_hat[c,j,b,s]
// thread = (s_ = tid&15, bq = tid>>4); 4 b's per thread, 40 acc chains.
// W pre-scaled by cc -> inner loop is pure 8-deep fma per (j,b).
// ---------------------------------------------------------------------------
__global__ void __launch_bounds__(256) k_s(const float* __restrict__ W) {
    extern __shared__ char smraw[];
    SMemS& sm = *(SMemS*)smraw;
    int c0 = blockIdx.x * CC;
    int b0 = blockIdx.y * BT;
    int tid = threadIdx.x;

    load_tiles<1>(W, c0, b0, tid, sm.Wsm, sm.xsm);
    __syncthreads();

    int s_ = tid & 15;
    int bb = (tid >> 4) * BPT;
    float acc[J][BPT];
    #pragma unroll
    for (int j = 0; j < J; j++)
        #pragma unroll
        for (int t = 0; t < BPT; t++) acc[j][t] = 0.f;

    #pragma unroll
    for (int cl = 0; cl < CC; ++cl) {
        float4 xa[BPT], xb[BPT];
        #pragma unroll
        for (int t = 0; t < BPT; t++) {
            xa[t] = sm.xsm[cl][bb + t][0];
            xb[t] = sm.xsm[cl][bb + t][1];
        }
        #pragma unroll
        for (int j = 0; j < J; j++) {
            float4 wa = sm.Wsm[cl][j][0][s_];
            float4 wb = sm.Wsm[cl][j][1][s_];
            #pragma unroll
            for (int t = 0; t < BPT; t++) {
                float a = acc[j][t];
                a = fmaf(wa.x, xa[t].x, a);
                a = fmaf(wa.y, xa[t].y, a);
                a = fmaf(wa.z, xa[t].z, a);
                a = fmaf(wa.w, xa[t].w, a);
                a = fmaf(wb.x, xb[t].x, a);
                a = fmaf(wb.y, xb[t].y, a);
                a = fmaf(wb.z, xb[t].z, a);
                a = fmaf(wb.w, xb[t].w, a);
                acc[j][t] = a;
            }
        }
    }
    float* sp = g_sp[blockIdx.x];
    #pragma unroll
    for (int j = 0; j < J; j++)
        #pragma unroll
        for (int t = 0; t < BPT; t++)
            sp[(j * B + b0 + bb + t) * S + s_] = acc[j][t];
}

// ---------------------------------------------------------------------------
// K_b: partial delta_b[c,j] = sum_{b,s in tile} v[j,b,s] * u_hat[c,j,b,s]
// full-warp shfl reduce (16s x 8b per warp) then one smem atomic per warp.
// Single __syncthreads at the end (dsm[CC][J] accumulator array).
// ---------------------------------------------------------------------------
__global__ void __launch_bounds__(256) k_b(const float* __restrict__ W) {
    extern __shared__ char smraw[];
    SMemB& sm = *(SMemB*)smraw;
    int c0 = blockIdx.x * CC;
    int b0 = blockIdx.y * BT;
    int tid = threadIdx.x;

    load_tiles<0>(W, c0, b0, tid, sm.Wsm, sm.xsm);
    if (tid < CC * J) sm.dsm[tid / J][tid % J] = 0.f;
    __syncthreads();

    int s_ = tid & 15;
    int bb = (tid >> 4) * BPT;
    float vv[J][BPT];
    #pragma unroll
    for (int j = 0; j < J; j++)
        #pragma unroll
        for (int t = 0; t < BPT; t++)
            vv[j][t] = g_v[(j * B + b0 + bb + t) * S + s_];

    #pragma unroll
    for (int cl = 0; cl < CC; ++cl) {
        float4 xa[BPT], xb[BPT];
        #pragma unroll
        for (int t = 0; t < BPT; t++) {
            xa[t] = sm.xsm[cl][bb + t][0];
            xb[t] = sm.xsm[cl][bb + t][1];
        }
        #pragma unroll
        for (int j = 0; j < J; j++) {
            float4 wa = sm.Wsm[cl][j][0][s_];
            float4 wb = sm.Wsm[cl][j][1][s_];
            float p = 0.f;
            #pragma unroll
            for (int t = 0; t < BPT; t++) {
                float u;
                u = wa.x * xa[t].x;
                u = fmaf(wa.y, xa[t].y, u);
                u = fmaf(wa.z, xa[t].z, u);
                u = fmaf(wa.w, xa[t].w, u);
                u = fmaf(wb.x, xb[t].x, u);
                u = fmaf(wb.y, xb[t].y, u);
                u = fmaf(wb.z, xb[t].z, u);
                u = fmaf(wb.w, xb[t].w, u);
                p = fmaf(vv[j][t], u, p);
            }
            p += __shfl_xor_sync(0xffffffffu, p, 1);
            p += __shfl_xor_sync(0xffffffffu, p, 2);
            p += __shfl_xor_sync(0xffffffffu, p, 4);
            p += __shfl_xor_sync(0xffffffffu, p, 8);
            p += __shfl_xor_sync(0xffffffffu, p, 16);
            if ((tid & 31) == 0) atomicAdd(&sm.dsm[cl][j], p);
        }
    }
    __syncthreads();
    if (tid < CC * J)
        g_bp[blockIdx.y][(c0 + tid / J) * J + tid % J] = sm.dsm[tid / J][tid % J];
}

// ---------------------------------------------------------------------------
// Reduce 144 partials -> s, squash over unit_size (16 lanes, shfl), -> v.
// ---------------------------------------------------------------------------
__global__ void k_rs(float* __restrict__ out) {
    int idx = blockIdx.x * blockDim.x + threadIdx.x;   // exactly J*B*S threads
    float sum = 0.f;
    #pragma unroll 8
    for (int p = 0; p < NC; p++) sum += g_sp[p][idx];
    float msq = sum * sum;
    msq += __shfl_xor_sync(0xffffffffu, msq, 1);
    msq += __shfl_xor_sync(0xffffffffu, msq, 2);
    msq += __shfl_xor_sync(0xffffffffu, msq, 4);
    msq += __shfl_xor_sync(0xffffffffu, msq, 8);
    float v = sum * sqrtf(msq) / (1.f + msq);
    g_v[idx] = v;
    if (out) {
        int s_ = idx & 15;
        int jb = idx >> 4;
        int b  = jb & (B - 1);
        int j  = jb >> 9;
        out[(b * J + j) * S + s_] = v;
    }
}

// ---------------------------------------------------------------------------
extern "C" void kernel_launch(void* const* d_in, const int* in_sizes, int n_in,
                              void* d_out, int out_size) {
    const float* x = (const float*)d_in[0];   // [512][8][1152]
    const float* W = (const float*)d_in[1];   // [1152][10][16][8]
    float* out = (float*)d_out;               // [512][10][16]

    cudaFuncSetAttribute(k_s, cudaFuncAttributeMaxDynamicSharedMemorySize,
                         (int)sizeof(SMemS));
    cudaFuncSetAttribute(k_b, cudaFuncAttributeMaxDynamicSharedMemorySize,
                         (int)sizeof(SMemB));

    k_transpose<<<dim3(C / 32, R / 32), dim3(32, 8)>>>(x);
    k_zero_b<<<(C * J + 255) / 256, 256>>>();

    for (int t = 0; t < NR; t++) {
        if (t > 0) k_b<<<dim3(NC, NB), 256, sizeof(SMemB)>>>(W);
        k_update_softmax<<<(C + 127) / 128, 128>>>(t > 0 ? 1 : 0);
        k_s<<<dim3(NC, NB), 256, sizeof(SMemS)>>>(W);
        k_rs<<<(J * B * S) / 256, 256>>>(t == NR - 1 ? out : nullptr);
    }
}

// round 3
// speedup vs baseline: 3.8004x; 1.3575x over previous
#include <cuda_runtime.h>
#include <math.h>

typedef unsigned long long ull;

// Problem constants
#define B    512
#define IU   8
#define C    1152
#define J    10
#define S    16
#define NR   3
#define R    (B*IU)      // 4096

// Tiling
#define CSPAN 32         // c's per block
#define NCG   (C/CSPAN)  // 36 c-groups
#define NSUB  4          // subchunks per block (8 c's each)
#define CCB   8          // c's per subchunk
#define BT    128        // b's per block
#define NB    (B/BT)     // 4 b-tiles
#define NTHR  512

// Scratch (__device__ globals; no allocation)
__device__ __align__(16) float g_xT[(size_t)C*B*IU];    // x transposed [c][b*8+i]
__device__ float g_b[C*J];
__device__ float g_cc[C*J];
__device__ ull   g_sp2[NCG][(size_t)J*B*8];              // packed s partials (s, s+8)
__device__ ull   g_v2[(size_t)J*B*8];                    // packed v
__device__ float g_bp[NB][C*J];                          // delta_b partials

// SMEM: W packed-interleaved + x duplicated + dsm for k_b
#define WJSTRIDE 72      // ull per (c,j) row, padded from 64 to break bank conflicts
struct SMem {
    ull   Wp[CCB * J * WJSTRIDE];   // [(cl*J+j)*72 + i*8 + sh] = (W[c,j,sh,i], W[c,j,sh+8,i])
    ull   xd[CCB * BT * 8];         // [(cl*128+bl)*8 + i] = (x, x)
    float dsm[16 * CCB * J];        // per-warp delta partials (k_b only)
};

// ---- packed f32x2 helpers ------------------------------------------------
__device__ __forceinline__ void fma2(ull& d, ull a, ull b) {
    asm("fma.rn.f32x2 %0, %1, %2, %0;" : "+l"(d) : "l"(a), "l"(b));
}
__device__ __forceinline__ ull add2(ull a, ull b) {
    ull d; asm("add.rn.f32x2 %0, %1, %2;" : "=l"(d) : "l"(a), "l"(b)); return d;
}
__device__ __forceinline__ ull pack2(float lo, float hi) {
    return ((ull)__float_as_uint(hi) << 32) | (ull)__float_as_uint(lo);
}
__device__ __forceinline__ ull dup2(float f) {
    unsigned u = __float_as_uint(f); return ((ull)u << 32) | (ull)u;
}
__device__ __forceinline__ float lo2(ull v) { return __uint_as_float((unsigned)v); }
__device__ __forceinline__ float hi2(ull v) { return __uint_as_float((unsigned)(v >> 32)); }

// ---------------------------------------------------------------------------
// Transpose x[b][i][c] -> g_xT[c][b*8+i]
// ---------------------------------------------------------------------------
__global__ void k_transpose(const float* __restrict__ x) {
    __shared__ float t[32][33];
    int cb = blockIdx.x * 32, rb = blockIdx.y * 32;
    int tx = threadIdx.x, ty = threadIdx.y;
    #pragma unroll
    for (int k = 0; k < 32; k += 8)
        t[ty + k][tx] = x[(size_t)(rb + ty + k) * C + cb + tx];
    __syncthreads();
    #pragma unroll
    for (int k = 0; k < 32; k += 8)
        g_xT[(size_t)(cb + ty + k) * R + rb + tx] = t[tx][ty + k];
}

__global__ void k_zero_b() {
    int i = blockIdx.x * blockDim.x + threadIdx.x;
    if (i < C * J) g_b[i] = 0.f;
}

// ---------------------------------------------------------------------------
// b += sum(partials)/B (if do_update), then cc = softmax_j(b) per c.
// ---------------------------------------------------------------------------
__global__ void k_update_softmax() {
    int c = blockIdx.x * blockDim.x + threadIdx.x;
    if (c >= C) return;
    float bv[J];
    #pragma unroll
    for (int j = 0; j < J; j++) {
        float v = g_b[c * J + j];
        float d = 0.f;
        #pragma unroll
        for (int p = 0; p < NB; p++) d += g_bp[p][c * J + j];
        v += d * (1.f / B);
        g_b[c * J + j] = v;
        bv[j] = v;
    }
    float m = bv[0];
    #pragma unroll
    for (int j = 1; j < J; j++) m = fmaxf(m, bv[j]);
    float sum = 0.f;
    #pragma unroll
    for (int j = 0; j < J; j++) { bv[j] = expf(bv[j] - m); sum += bv[j]; }
    float inv = 1.f / sum;
    #pragma unroll
    for (int j = 0; j < J; j++) g_cc[c * J + j] = bv[j] * inv;
}

// ---------------------------------------------------------------------------
// Subchunk loader: transform W into s-pair-interleaved layout (optionally
// pre-scaled by cc), and x into (x,x)-duplicated layout.
// ---------------------------------------------------------------------------
template <int WITH_CC>
__device__ __forceinline__ void load_tiles(
    const float* __restrict__ W, int c0, int b0, int tid, ull* Wp, ull* xd)
{
    const float4* Wg = (const float4*)W;
    // 1280 W tasks: (cl, j, sh, ih)
    for (int task = tid; task < CCB * J * 8 * 2; task += NTHR) {
        int ih = task & 1, sh = (task >> 1) & 7;
        int t4 = task >> 4;
        int j  = t4 % J;
        int cl = t4 / J;
        int c  = c0 + cl;
        int base = (c * J + j) * 16;
        float4 a = Wg[(base + sh) * 2 + ih];
        float4 b = Wg[(base + sh + 8) * 2 + ih];
        if (WITH_CC) {
            float cv = __ldg(&g_cc[c * J + j]);
            a.x *= cv; a.y *= cv; a.z *= cv; a.w *= cv;
            b.x *= cv; b.y *= cv; b.z *= cv; b.w *= cv;
        }
        ull* wdst = Wp + (cl * J + j) * WJSTRIDE + (ih * 4) * 8 + sh;
        wdst[0]  = pack2(a.x, b.x);
        wdst[8]  = pack2(a.y, b.y);
        wdst[16] = pack2(a.z, b.z);
        wdst[24] = pack2(a.w, b.w);
    }
    // 2048 x tasks: (cl, bl, ih)
    for (int task = tid; task < CCB * BT * 2; task += NTHR) {
        int ih = task & 1, bl = (task >> 1) & (BT - 1), cl = task >> 8;
        const float4* xg = (const float4*)(g_xT + (size_t)(c0 + cl) * R
                                                + (size_t)(b0 + bl) * IU);
        float4 v = xg[ih];
        ulonglong2* d = (ulonglong2*)(xd + (cl * BT + bl) * 8 + ih * 4);
        d[0] = make_ulonglong2(dup2(v.x), dup2(v.y));
        d[1] = make_ulonglong2(dup2(v.z), dup2(v.w));
    }
}

// ---------------------------------------------------------------------------
// K_s: partial s over this block's 32 c's, packed f32x2 over (s, s+8).
// Thread: sh = tid&7, jg = (tid>>3)&1 (j-half), bt = tid>>4 (b-quad).
// ---------------------------------------------------------------------------
template <int WITH_CC>
__global__ void __launch_bounds__(NTHR, 1) k_s(const float* __restrict__ W) {
    extern __shared__ char smraw[];
    SMem& sm = *(SMem*)smraw;
    int tid = threadIdx.x;
    int cbase = blockIdx.x * CSPAN;
    int b0    = blockIdx.y * BT;
    int sh = tid & 7;
    int jb = ((tid >> 3) & 1) * 5;
    int bt = tid >> 4;          // 0..31

    ull acc[5][4];
    #pragma unroll
    for (int jj = 0; jj < 5; jj++)
        #pragma unroll
        for (int t = 0; t < 4; t++) acc[jj][t] = 0ull;

    for (int sc = 0; sc < NSUB; sc++) {
        __syncthreads();
        load_tiles<WITH_CC>(W, cbase + sc * CCB, b0, tid, sm.Wp, sm.xd);
        __syncthreads();
        #pragma unroll
        for (int cl = 0; cl < CCB; cl++) {
            const ull* xrow = sm.xd + (cl * BT + bt * 4) * 8;
            #pragma unroll
            for (int ih = 0; ih < 2; ih++) {
                ulonglong2 xA[4], xB[4];
                #pragma unroll
                for (int t = 0; t < 4; t++) {
                    const ulonglong2* xp = (const ulonglong2*)(xrow + t * 8 + ih * 4);
                    xA[t] = xp[0]; xB[t] = xp[1];
                }
                const ull* wb_ = sm.Wp + (cl * J + jb) * WJSTRIDE + ih * 32 + sh;
                #pragma unroll
                for (int jj = 0; jj < 5; jj++) {
                    const ull* w = wb_ + jj * WJSTRIDE;
                    ull w0 = w[0], w1 = w[8], w2 = w[16], w3 = w[24];
                    #pragma unroll
                    for (int t = 0; t < 4; t++) {
                        fma2(acc[jj][t], w0, xA[t].x);
                        fma2(acc[jj][t], w1, xA[t].y);
                        fma2(acc[jj][t], w2, xB[t].x);
                        fma2(acc[jj][t], w3, xB[t].y);
                    }
                }
            }
        }
    }
    ull* sp = g_sp2[blockIdx.x];
    #pragma unroll
    for (int jj = 0; jj < 5; jj++)
        #pragma unroll
        for (int t = 0; t < 4; t++)
            sp[((size_t)(jb + jj) * B + b0 + bt * 4 + t) * 8 + sh] = acc[jj][t];
}

// ---------------------------------------------------------------------------
// K_b: delta_b[c,j] = sum_{b,s} v * u_hat, via y_i = sum_t v_t x_{t,i},
// then p += w_i * y_i (packed). Reduce over sh (xor 1,2,4) + bt-pair (xor 16).
// ---------------------------------------------------------------------------
__global__ void __launch_bounds__(NTHR, 1) k_b(const float* __restrict__ W) {
    extern __shared__ char smraw[];
    SMem& sm = *(SMem*)smraw;
    int tid = threadIdx.x;
    int cbase = blockIdx.x * CSPAN;
    int b0    = blockIdx.y * BT;
    int sh = tid & 7;
    int jb = ((tid >> 3) & 1) * 5;
    int bt = tid >> 4;
    int warp = tid >> 5;
    int lane = tid & 31;

    ull vv2[5][4];
    #pragma unroll
    for (int jj = 0; jj < 5; jj++)
        #pragma unroll
        for (int t = 0; t < 4; t++)
            vv2[jj][t] = g_v2[((size_t)(jb + jj) * B + b0 + bt * 4 + t) * 8 + sh];

    for (int sc = 0; sc < NSUB; sc++) {
        __syncthreads();
        load_tiles<0>(W, cbase + sc * CCB, b0, tid, sm.Wp, sm.xd);
        __syncthreads();
        #pragma unroll 1
        for (int cl = 0; cl < CCB; cl++) {
            ull p2[5];
            #pragma unroll
            for (int jj = 0; jj < 5; jj++) p2[jj] = 0ull;
            const ull* xrow = sm.xd + (cl * BT + bt * 4) * 8;
            #pragma unroll
            for (int ih = 0; ih < 2; ih++) {
                ulonglong2 xA[4], xB[4];
                #pragma unroll
                for (int t = 0; t < 4; t++) {
                    const ulonglong2* xp = (const ulonglong2*)(xrow + t * 8 + ih * 4);
                    xA[t] = xp[0]; xB[t] = xp[1];
                }
                const ull* wb_ = sm.Wp + (cl * J + jb) * WJSTRIDE + ih * 32 + sh;
                #pragma unroll
                for (int jj = 0; jj < 5; jj++) {
                    const ull* w = wb_ + jj * WJSTRIDE;
                    ull y0 = 0, y1 = 0, y2 = 0, y3 = 0;
                    #pragma unroll
                    for (int t = 0; t < 4; t++) {
                        fma2(y0, vv2[jj][t], xA[t].x);
                        fma2(y1, vv2[jj][t], xA[t].y);
                        fma2(y2, vv2[jj][t], xB[t].x);
                        fma2(y3, vv2[jj][t], xB[t].y);
                    }
                    fma2(p2[jj], w[0],  y0);
                    fma2(p2[jj], w[8],  y1);
                    fma2(p2[jj], w[16], y2);
                    fma2(p2[jj], w[24], y3);
                }
            }
            #pragma unroll
            for (int jj = 0; jj < 5; jj++) {
                float p = lo2(p2[jj]) + hi2(p2[jj]);
                p += __shfl_xor_sync(0xffffffffu, p, 1);
                p += __shfl_xor_sync(0xffffffffu, p, 2);
                p += __shfl_xor_sync(0xffffffffu, p, 4);
                p += __shfl_xor_sync(0xffffffffu, p, 16);
                if ((lane & 23) == 0)   // lanes 0 (jg0) and 8 (jg1)
                    sm.dsm[(warp * CCB + cl) * J + jb + jj] = p;
            }
        }
        __syncthreads();
        if (tid < CCB * J) {
            int cl = tid / J, j = tid % J;
            float sacc = 0.f;
            #pragma unroll
            for (int w = 0; w < 16; w++) sacc += sm.dsm[(w * CCB + cl) * J + j];
            atomicAdd(&g_bp[blockIdx.y][(cbase + sc * CCB + cl) * J + j], 0.f);
            g_bp[blockIdx.y][(cbase + sc * CCB + cl) * J + j] = sacc;
        }
    }
}

// ---------------------------------------------------------------------------
// Reduce NCG packed partials -> s, squash, -> packed v (+ optional output).
// postscale folds the uniform cc=1/J of iteration 0.
// ---------------------------------------------------------------------------
__global__ void k_rs(float postscale, float* __restrict__ out) {
    int idx = blockIdx.x * blockDim.x + threadIdx.x;   // J*B*8 threads
    ull a = 0ull;
    #pragma unroll 6
    for (int p = 0; p < NCG; p++) a = add2(a, g_sp2[p][idx]);
    float lo = lo2(a) * postscale;
    float hi = hi2(a) * postscale;
    float m = lo * lo + hi * hi;
    m += __shfl_xor_sync(0xffffffffu, m, 1);
    m += __shfl_xor_sync(0xffffffffu, m, 2);
    m += __shfl_xor_sync(0xffffffffu, m, 4);
    float fac = sqrtf(m) / (1.f + m);
    float vlo = lo * fac, vhi = hi * fac;
    g_v2[idx] = pack2(vlo, vhi);
    if (out) {
        int sh = idx & 7;
        int b  = (idx >> 3) & (B - 1);
        int j  = idx >> 12;
        out[(b * J + j) * S + sh]     = vlo;
        out[(b * J + j) * S + sh + 8] = vhi;
    }
}

// ---------------------------------------------------------------------------
extern "C" void kernel_launch(void* const* d_in, const int* in_sizes, int n_in,
                              void* d_out, int out_size) {
    const float* x = (const float*)d_in[0];   // [512][8][1152]
    const float* W = (const float*)d_in[1];   // [1152][10][16][8]
    float* out = (float*)d_out;               // [512][10][16]

    cudaFuncSetAttribute(k_s<0>, cudaFuncAttributeMaxDynamicSharedMemorySize,
                         (int)sizeof(SMem));
    cudaFuncSetAttribute(k_s<1>, cudaFuncAttributeMaxDynamicSharedMemorySize,
                         (int)sizeof(SMem));
    cudaFuncSetAttribute(k_b, cudaFuncAttributeMaxDynamicSharedMemorySize,
                         (int)sizeof(SMem));

    k_transpose<<<dim3(C / 32, R / 32), dim3(32, 8)>>>(x);
    k_zero_b<<<(C * J + 255) / 256, 256>>>();

    dim3 grid(NCG, NB);
    // t = 0: cc uniform (1/J) -> skip softmax, fold into k_rs postscale
    k_s<0><<<grid, NTHR, sizeof(SMem)>>>(W);
    k_rs<<<(J * B * 8) / 256, 256>>>(0.1f, nullptr);
    for (int t = 1; t < NR; t++) {
        k_b<<<grid, NTHR, sizeof(SMem)>>>(W);
        k_update_softmax<<<(C + 127) / 128, 128>>>();
        k_s<1><<<grid, NTHR, sizeof(SMem)>>>(W);
        k_rs<<<(J * B * 8) / 256, 256>>>(1.f, t == NR - 1 ? out : nullptr);
    }
}